// round 6
// baseline (speedup 1.0000x reference)
#include <cuda_runtime.h>

// ---------------------------------------------------------------------------
// ImprovedAILayerNorm: int8-quantized layernorm with LUT integer sqrt.
// R6: warp-per-row reductions (NO __syncthreads, NO smem) in pass1/pass2 so
// the LDG stream never drains behind block barriers. Integer row sums are
// exact => bit-identical stats vs block reduction. Serpentine + ldcs/stcs
// kept. init+check fused into one launch.
// ---------------------------------------------------------------------------

#define T2 512
#define WPB (T2 / 32)            // 16 warps (rows) per block
#define MAX_ROWS 32768

__device__ int   g_absmax_bits;
__device__ int   g_ymax_bits;
__device__ int   g_const_flag;
__device__ float g_g0, g_b0;
__device__ float g_mu[MAX_ROWS];
__device__ float g_inv_std[MAX_ROWS];
__device__ float g_rowmin[MAX_ROWS];
__device__ float g_rowmax[MAX_ROWS];

// ---------------------------------------------------------------------------
// init + gamma/beta const check, single block
__global__ void k_init_check(const float* __restrict__ gamma,
                             const float* __restrict__ beta, int N) {
    if (threadIdx.x == 0) {
        g_absmax_bits = 0;
        g_ymax_bits   = 0;
        g_const_flag  = 1;
        g_g0 = gamma[0];
        g_b0 = beta[0];
    }
    __syncthreads();
    float g0 = g_g0, b0 = g_b0;
    bool bad = false;
    for (int i = threadIdx.x; i < N; i += blockDim.x)
        bad |= (gamma[i] != g0) || (beta[i] != b0);
    if (__syncthreads_or(bad) && threadIdx.x == 0) g_const_flag = 0;
}

// ---------------------------------------------------------------------------
// Pass 1: warp-per-row min/max + global absmax. ASCENDING rows.
__global__ void __launch_bounds__(T2)
k_absmax(const float* __restrict__ x, int N) {
    const int warp = threadIdx.x >> 5;
    const int lane = threadIdx.x & 31;
    const int row  = blockIdx.x * WPB + warp;
    const int NW   = N / (32 * 4);                     // 8 iters for N=4096
    const float4* xr = reinterpret_cast<const float4*>(x + (size_t)row * N);

    float mn = 3.4e38f, mx = -3.4e38f;
    #pragma unroll
    for (int j = 0; j < NW; j++) {
        float4 v = xr[j * 32 + lane];
        mn = fminf(mn, fminf(fminf(v.x, v.y), fminf(v.z, v.w)));
        mx = fmaxf(mx, fmaxf(fmaxf(v.x, v.y), fmaxf(v.z, v.w)));
    }
    // warp min/max via bit tricks on floats (monotone maps), no loop shuffles
    // max: flip sign bit for negatives -> order-preserving uint
    unsigned umx = __float_as_uint(mx);
    umx = (umx & 0x80000000u) ? ~umx : (umx | 0x80000000u);
    umx = __reduce_max_sync(0xffffffffu, umx);
    unsigned umn = __float_as_uint(mn);
    umn = (umn & 0x80000000u) ? ~umn : (umn | 0x80000000u);
    umn = __reduce_min_sync(0xffffffffu, umn);
    if (lane == 0) {
        float fmx = __uint_as_float((umx & 0x80000000u) ? (umx & 0x7fffffffu) : ~umx);
        float fmn = __uint_as_float((umn & 0x80000000u) ? (umn & 0x7fffffffu) : ~umn);
        g_rowmin[row] = fmn;
        g_rowmax[row] = fmx;
        float am = fmaxf(fabsf(fmn), fabsf(fmx));
        atomicMax(&g_absmax_bits, (int)__float_as_uint(am));
    }
}

// ---------------------------------------------------------------------------
// Exact replica of reference sqrt_rounded_vec (LUT-based rounded int sqrt)
__device__ __forceinline__ float sqrt_rounded(int d) {
    int msb = 31 - __clz(d);
    int k   = msb >> 1;
    int dn  = d << ((7 - k) * 2);
    int addr = (dn >> 8) & 255;
    int v    = addr * 256 + 128;
    int mant = (int)sqrtf((float)v);
    if (mant * mant > v) mant--;
    if ((mant + 1) * (mant + 1) <= v) mant++;
    int qf = mant >> (7 - k);
    int boundary = qf * qf + qf;
    return (float)((d > boundary) ? qf + 1 : qf);
}

// ---------------------------------------------------------------------------
// Pass 2: warp-per-row int moments, DESCENDING rows. No barriers, no clamps
// (|x|/s <= 127 by construction of s). Const path: ymax from rowmin/rowmax.
__global__ void __launch_bounds__(T2)
k_rowstats(const float* __restrict__ x,
           const float* __restrict__ gamma,
           const float* __restrict__ beta,
           int N, int rows) {
    const int warp = threadIdx.x >> 5;
    const int lane = threadIdx.x & 31;
    const int row  = rows - 1 - (blockIdx.x * WPB + warp);   // descending
    const int NW   = N / (32 * 4);
    const float4* xr = reinterpret_cast<const float4*>(x + (size_t)row * N);
    const bool cst = (g_const_flag != 0);

    const float s     = fmaxf(__int_as_float(g_absmax_bits) / 127.0f, 1e-8f);
    const float inv_s = 1.0f / s;

    int isum = 0, isum2 = 0;
    #pragma unroll
    for (int j = 0; j < NW; j++) {
        float4 v = xr[j * 32 + lane];
        #pragma unroll
        for (int c = 0; c < 4; c++) {
            int q = __float2int_rn((&v.x)[c] * inv_s);  // RN half-even
            isum  += q;
            isum2 += q * q;
        }
    }
    int t  = __reduce_add_sync(0xffffffffu, isum);
    int t2 = __reduce_add_sync(0xffffffffu, isum2);

    float mu, inv;
    if (lane == 0) {
        float Ex  = (float)t  * s;
        float Ex2 = (float)t2 * (s * s);
        mu  = Ex / (float)N;
        float var = fmaxf(Ex2 / (float)N - mu * mu, 0.0f);
        float vi  = fminf(fmaxf(rintf(var), 1.0f), 65535.0f);
        float std_i = sqrt_rounded((int)vi);
        inv = 1.0f / fmaxf(std_i, 1e-5f);
        g_mu[row] = mu;
        g_inv_std[row] = inv;
        if (cst) {
            float g0 = g_g0, b0 = g_b0;
            float y1 = fabsf((g_rowmax[row] - mu) * inv * g0 + b0);
            float y2 = fabsf((g_rowmin[row] - mu) * inv * g0 + b0);
            atomicMax(&g_ymax_bits, (int)__float_as_uint(fmaxf(y1, y2)));
        }
    }
    if (cst) return;

    // ---- general gamma/beta path: per-warp sweep for max|y| ----
    mu  = __shfl_sync(0xffffffffu, mu, 0);
    inv = __shfl_sync(0xffffffffu, inv, 0);
    const float4* g4 = reinterpret_cast<const float4*>(gamma);
    const float4* b4 = reinterpret_cast<const float4*>(beta);
    float ymax = 0.0f;
    #pragma unroll
    for (int j = 0; j < NW; j++) {
        float4 v = xr[j * 32 + lane];
        float4 g = g4[j * 32 + lane];
        float4 b = b4[j * 32 + lane];
        #pragma unroll
        for (int c = 0; c < 4; c++) {
            float y = ((&v.x)[c] - mu) * inv * (&g.x)[c] + (&b.x)[c];
            ymax = fmaxf(ymax, fabsf(y));
        }
    }
    unsigned yb = __reduce_max_sync(0xffffffffu, __float_as_uint(ymax));
    if (lane == 0) atomicMax(&g_ymax_bits, (int)yb);
}

// ---------------------------------------------------------------------------
// Pass 3: block-per-row (no barriers anyway), ASCENDING rows.
// x via __ldcs (last use), out via __stcs (streaming).
__global__ void __launch_bounds__(T2)
k_quant(const float* __restrict__ x,
        const float* __restrict__ gamma,
        const float* __restrict__ beta,
        float* __restrict__ out,
        int N) {
    const int row = blockIdx.x;
    const int NIT = 2;
    const float4* xr = reinterpret_cast<const float4*>(x + (size_t)row * N);
    float4* orow = reinterpret_cast<float4*>(out + (size_t)row * N);

    const float mu = g_mu[row];
    const float is = g_inv_std[row];
    const float so     = fmaxf(__int_as_float(g_ymax_bits) / 127.0f, 1e-8f);
    const float inv_so = 1.0f / so;

    if (g_const_flag) {
        const float g0 = g_g0, b0 = g_b0;
        const float A2 = is * g0 * inv_so;
        const float B2 = (b0 - mu * is * g0) * inv_so;
        #pragma unroll
        for (int j = 0; j < NIT; j++) {
            float4 v = __ldcs(&xr[j * T2 + threadIdx.x]);
            float4 o;
            #pragma unroll
            for (int c = 0; c < 4; c++) {
                int q = __float2int_rn(fmaf((&v.x)[c], A2, B2));
                q = max(-127, min(127, q));        // safety vs reassoc ulp
                (&o.x)[c] = (float)q * so;
            }
            __stcs(&orow[j * T2 + threadIdx.x], o);
        }
        return;
    }

    const float4* g4 = reinterpret_cast<const float4*>(gamma);
    const float4* b4 = reinterpret_cast<const float4*>(beta);
    #pragma unroll
    for (int j = 0; j < NIT; j++) {
        float4 v = __ldcs(&xr[j * T2 + threadIdx.x]);
        float4 g = g4[j * T2 + threadIdx.x];
        float4 b = b4[j * T2 + threadIdx.x];
        float4 o;
        #pragma unroll
        for (int c = 0; c < 4; c++) {
            float y = ((&v.x)[c] - mu) * is * (&g.x)[c] + (&b.x)[c];
            int q = __float2int_rn(y * inv_so);
            (&o.x)[c] = (float)q * so;
        }
        __stcs(&orow[j * T2 + threadIdx.x], o);
    }
}

// ---------------------------------------------------------------------------
extern "C" void kernel_launch(void* const* d_in, const int* in_sizes, int n_in,
                              void* d_out, int out_size) {
    const float* x     = (const float*)d_in[0];
    const float* gamma = (const float*)d_in[1];
    const float* beta  = (const float*)d_in[2];
    float* out = (float*)d_out;

    const int N    = in_sizes[1];        // 4096
    const int n    = in_sizes[0];        // 4*2048*4096
    const int rows = n / N;              // 8192

    k_init_check<<<1, T2>>>(gamma, beta, N);
    k_absmax<<<rows / WPB, T2>>>(x, N);
    k_rowstats<<<rows / WPB, T2>>>(x, gamma, beta, N, rows);
    k_quant<<<rows, T2>>>(x, gamma, beta, out, N);
}